// round 2
// baseline (speedup 1.0000x reference)
#include <cuda_runtime.h>
#include <math.h>

#define BATCH 2
#define SEQ   2048
#define DIM   2048
#define NH    16
#define HDIM  128
#define NE    4
#define IDIM  2048
#define NTOK  (BATCH*SEQ)   // 4096

// ---------------- scratch (static device globals; no allocation in kernel_launch) ----
__device__ float g_ln   [(size_t)NTOK*DIM];
__device__ float g_q    [(size_t)NTOK*DIM];   // also reused as MoE hmid
__device__ float g_k    [(size_t)NTOK*DIM];
__device__ float g_v    [(size_t)NTOK*DIM];
__device__ float g_attn [(size_t)NTOK*DIM];
__device__ float g_comb [(size_t)NTOK*NE];

// ---------------- LayerNorm: one block per row ----------------
__global__ void ln_kernel(const float* __restrict__ x, const float* __restrict__ w,
                          const float* __restrict__ b, float* __restrict__ y) {
    int row = blockIdx.x;
    const float* xr = x + (size_t)row * DIM;
    float* yr = y + (size_t)row * DIM;
    __shared__ float red[256];
    int tid = threadIdx.x;
    float s = 0.f;
    for (int i = tid; i < DIM; i += 256) s += xr[i];
    red[tid] = s; __syncthreads();
    for (int o = 128; o > 0; o >>= 1) { if (tid < o) red[tid] += red[tid + o]; __syncthreads(); }
    float mu = red[0] * (1.f / DIM);
    __syncthreads();
    float v = 0.f;
    for (int i = tid; i < DIM; i += 256) { float d = xr[i] - mu; v += d * d; }
    red[tid] = v; __syncthreads();
    for (int o = 128; o > 0; o >>= 1) { if (tid < o) red[tid] += red[tid + o]; __syncthreads(); }
    float inv = rsqrtf(red[0] * (1.f / DIM) + 1e-5f);
    for (int i = tid; i < DIM; i += 256) yr[i] = (xr[i] - mu) * inv * w[i] + b[i];
}

// ---------------- Generic tiled GEMM (NN): C = act(A@B + bias) [+resid] [*rowscale] ----
__global__ void gemm_nn(const float* __restrict__ A, int lda,
                        const float* __restrict__ B, int ldb,
                        const float* __restrict__ bias,
                        float* __restrict__ C, int ldc,
                        const float* __restrict__ resid, int ldr,
                        const float* __restrict__ rowscale, int rss,
                        int M, int N, int K, int act, int accum) {
    __shared__ float As[16][68];
    __shared__ float Bs[16][68];
    int row0 = blockIdx.y * 64, col0 = blockIdx.x * 64;
    int tid = threadIdx.x, tx = tid & 15, ty = tid >> 4;
    float acc[4][4];
#pragma unroll
    for (int i = 0; i < 4; i++)
#pragma unroll
        for (int j = 0; j < 4; j++) acc[i][j] = 0.f;
    for (int k0 = 0; k0 < K; k0 += 16) {
#pragma unroll
        for (int i = tid; i < 64 * 16; i += 256) {
            int m = i >> 4, kk = i & 15;
            As[kk][m] = A[(size_t)(row0 + m) * lda + k0 + kk];
        }
#pragma unroll
        for (int i = tid; i < 16 * 64; i += 256) {
            int kk = i >> 6, n = i & 63;
            Bs[kk][n] = B[(size_t)(k0 + kk) * ldb + col0 + n];
        }
        __syncthreads();
#pragma unroll
        for (int kk = 0; kk < 16; kk++) {
            float a0 = As[kk][ty * 4 + 0], a1 = As[kk][ty * 4 + 1];
            float a2 = As[kk][ty * 4 + 2], a3 = As[kk][ty * 4 + 3];
            float b0 = Bs[kk][tx * 4 + 0], b1 = Bs[kk][tx * 4 + 1];
            float b2 = Bs[kk][tx * 4 + 2], b3 = Bs[kk][tx * 4 + 3];
            acc[0][0] += a0 * b0; acc[0][1] += a0 * b1; acc[0][2] += a0 * b2; acc[0][3] += a0 * b3;
            acc[1][0] += a1 * b0; acc[1][1] += a1 * b1; acc[1][2] += a1 * b2; acc[1][3] += a1 * b3;
            acc[2][0] += a2 * b0; acc[2][1] += a2 * b1; acc[2][2] += a2 * b2; acc[2][3] += a2 * b3;
            acc[3][0] += a3 * b0; acc[3][1] += a3 * b1; acc[3][2] += a3 * b2; acc[3][3] += a3 * b3;
        }
        __syncthreads();
    }
#pragma unroll
    for (int i = 0; i < 4; i++) {
        int gm = row0 + ty * 4 + i;
        size_t crow = (size_t)gm * ldc;
        float rs = rowscale ? rowscale[(size_t)gm * rss] : 1.f;
#pragma unroll
        for (int j = 0; j < 4; j++) {
            int gn = col0 + tx * 4 + j;
            float v = acc[i][j];
            if (bias) v += bias[gn];
            if (act == 1) v = 0.5f * v * (1.f + erff(v * 0.70710678118654752f));
            if (resid) v += resid[(size_t)gm * ldr + gn];
            v *= rs;
            if (accum) C[crow + gn] += v; else C[crow + gn] = v;
        }
    }
}

// ---------------- RoPE in-place on Q and K (double-precision trig; fast-math-proof) ----
__global__ void rope_kernel(float* __restrict__ q, float* __restrict__ k) {
    int idx = blockIdx.x * blockDim.x + threadIdx.x;   // over NTOK*NH*64
    if (idx >= NTOK * NH * 64) return;
    int i = idx & 63;
    int rem = idx >> 6;
    int h = rem % NH;
    int t = rem / NH;
    int s = t % SEQ;
    float invf = (float)(1.0 / pow(10000.0, (double)i / 64.0));
    float ang = (float)s * invf;              // fp32 angle, like the reference
    double angd = (double)ang;
    float c  = (float)cos(angd);              // exact trig of that fp32 angle
    float sn = (float)sin(angd);
    size_t base = (size_t)t * DIM + (size_t)h * HDIM;
    float q1 = q[base + i], q2 = q[base + 64 + i];
    q[base + i]      = q1 * c - q2 * sn;
    q[base + 64 + i] = q2 * c + q1 * sn;
    float k1 = k[base + i], k2 = k[base + 64 + i];
    k[base + i]      = k1 * c - k2 * sn;
    k[base + 64 + i] = k2 * c + k1 * sn;
}

// ---------------- Fused causal attention: one warp per (b, h, query row) --------------
// Online softmax; out[q] = softmax(q.K^T / sqrt(HD)) @ V over k in [0, q].
__global__ void attn_kernel(const float* __restrict__ q, const float* __restrict__ k,
                            const float* __restrict__ v, float* __restrict__ attn) {
    int gw = (blockIdx.x * blockDim.x + threadIdx.x) >> 5;   // global warp id
    int lane = threadIdx.x & 31;
    if (gw >= BATCH * NH * SEQ) return;
    int qpos = gw % SEQ;
    int h = (gw / SEQ) % NH;
    int b = gw / (SEQ * NH);
    const float alpha = 0.08838834764831845f;   // 1/sqrt(128)

    const float4* q4 = (const float4*)(q + ((size_t)(b * SEQ + qpos)) * DIM + h * HDIM);
    float4 qv = q4[lane];

    float m = -3.0e38f, l = 0.f;
    float4 acc = make_float4(0.f, 0.f, 0.f, 0.f);

    const float* kbase = k + ((size_t)b * SEQ) * DIM + h * HDIM;
    const float* vbase = v + ((size_t)b * SEQ) * DIM + h * HDIM;

    for (int kp = 0; kp <= qpos; kp++) {
        const float4* k4 = (const float4*)(kbase + (size_t)kp * DIM);
        float4 kk = k4[lane];
        float s = qv.x * kk.x + qv.y * kk.y + qv.z * kk.z + qv.w * kk.w;
#pragma unroll
        for (int off = 16; off > 0; off >>= 1)
            s += __shfl_xor_sync(0xffffffffu, s, off);
        s *= alpha;
        float mn = fmaxf(m, s);
        float corr = expf(m - mn);    // first iter: exp(-huge) = 0
        float p = expf(s - mn);
        l = l * corr + p;
        const float4* v4 = (const float4*)(vbase + (size_t)kp * DIM);
        float4 vv = v4[lane];
        acc.x = acc.x * corr + p * vv.x;
        acc.y = acc.y * corr + p * vv.y;
        acc.z = acc.z * corr + p * vv.z;
        acc.w = acc.w * corr + p * vv.w;
        m = mn;
    }
    float invl = 1.f / l;
    float4* o4 = (float4*)(attn + ((size_t)(b * SEQ + qpos)) * DIM + h * HDIM);
    o4[lane] = make_float4(acc.x * invl, acc.y * invl, acc.z * invl, acc.w * invl);
}

// ---------------- MoE gate: softmax -> top2 -> renormalized softmax --------------------
__global__ void gate_kernel(const float* __restrict__ x, const float* __restrict__ wg,
                            float* __restrict__ comb) {
    int t = blockIdx.x;
    int tid = threadIdx.x;
    __shared__ float red[NE * 128];
    const float* xr = x + (size_t)t * DIM;
    float acc[NE] = {0.f, 0.f, 0.f, 0.f};
    for (int d = tid; d < DIM; d += 128) {
        float xv = xr[d];
#pragma unroll
        for (int e = 0; e < NE; e++) acc[e] += xv * wg[(size_t)d * NE + e];
    }
#pragma unroll
    for (int e = 0; e < NE; e++) red[e * 128 + tid] = acc[e];
    __syncthreads();
    for (int o = 64; o > 0; o >>= 1) {
        if (tid < o) {
#pragma unroll
            for (int e = 0; e < NE; e++) red[e * 128 + tid] += red[e * 128 + tid + o];
        }
        __syncthreads();
    }
    if (tid == 0) {
        float l[NE];
#pragma unroll
        for (int e = 0; e < NE; e++) l[e] = red[e * 128];
        float mx = fmaxf(fmaxf(l[0], l[1]), fmaxf(l[2], l[3]));
        float ex[NE], s = 0.f;
#pragma unroll
        for (int e = 0; e < NE; e++) { ex[e] = expf(l[e] - mx); s += ex[e]; }
        float p[NE];
#pragma unroll
        for (int e = 0; e < NE; e++) p[e] = ex[e] / s;
        int i0 = 0;
#pragma unroll
        for (int e = 1; e < NE; e++) if (p[e] > p[i0]) i0 = e;
        int i1 = (i0 == 0) ? 1 : 0;
#pragma unroll
        for (int e = 0; e < NE; e++) if (e != i0 && p[e] > p[i1]) i1 = e;
        float e1 = expf(p[i1] - p[i0]);     // softmax over the two top probabilities
        float invs = 1.f / (1.f + e1);
        float c[NE] = {0.f, 0.f, 0.f, 0.f};
        c[i0] = invs;
        c[i1] = e1 * invs;
#pragma unroll
        for (int e = 0; e < NE; e++) comb[(size_t)t * NE + e] = c[e];
    }
}

// ---------------- host orchestration ---------------------------------------------------
extern "C" void kernel_launch(void* const* d_in, const int* in_sizes, int n_in,
                              void* d_out, int out_size) {
    (void)in_sizes; (void)n_in; (void)out_size;
    const float* hs   = (const float*)d_in[0];
    const float* wq   = (const float*)d_in[1];
    const float* bq   = (const float*)d_in[2];
    const float* wk   = (const float*)d_in[3];
    const float* bk   = (const float*)d_in[4];
    const float* wv   = (const float*)d_in[5];
    const float* bv   = (const float*)d_in[6];
    const float* wo   = (const float*)d_in[7];
    const float* bo   = (const float*)d_in[8];
    const float* ln1w = (const float*)d_in[9];
    const float* ln1b = (const float*)d_in[10];
    const float* ln2w = (const float*)d_in[11];
    const float* ln2b = (const float*)d_in[12];
    const float* wg   = (const float*)d_in[13];
    const float* we1  = (const float*)d_in[14];
    const float* be1  = (const float*)d_in[15];
    const float* we2  = (const float*)d_in[16];
    const float* be2  = (const float*)d_in[17];
    float* out = (float*)d_out;

    float *p_ln, *p_q, *p_k, *p_v, *p_attn, *p_comb;
    cudaGetSymbolAddress((void**)&p_ln, g_ln);
    cudaGetSymbolAddress((void**)&p_q, g_q);
    cudaGetSymbolAddress((void**)&p_k, g_k);
    cudaGetSymbolAddress((void**)&p_v, g_v);
    cudaGetSymbolAddress((void**)&p_attn, g_attn);
    cudaGetSymbolAddress((void**)&p_comb, g_comb);

    // 1. LN1
    ln_kernel<<<NTOK, 256>>>(hs, ln1w, ln1b, p_ln);

    // 2. QKV projections
    dim3 gBig(DIM / 64, NTOK / 64, 1);
    gemm_nn<<<gBig, 256>>>(p_ln, DIM, wq, DIM, bq, p_q, DIM,
                           nullptr, 0, nullptr, 0, NTOK, DIM, DIM, 0, 0);
    gemm_nn<<<gBig, 256>>>(p_ln, DIM, wk, DIM, bk, p_k, DIM,
                           nullptr, 0, nullptr, 0, NTOK, DIM, DIM, 0, 0);
    gemm_nn<<<gBig, 256>>>(p_ln, DIM, wv, DIM, bv, p_v, DIM,
                           nullptr, 0, nullptr, 0, NTOK, DIM, DIM, 0, 0);

    // 3. RoPE on Q,K
    int nrope = NTOK * NH * 64;
    rope_kernel<<<(nrope + 255) / 256, 256>>>(p_q, p_k);

    // 4. Fused causal attention (scores+softmax+PV in one kernel)
    int nwarps = BATCH * NH * SEQ;                  // 65536 warps
    attn_kernel<<<(nwarps * 32) / 256, 256>>>(p_q, p_k, p_v, p_attn);

    // 5. O-proj + bias + residual(hidden) -> out  (= h)
    gemm_nn<<<gBig, 256>>>(p_attn, DIM, wo, DIM, bo, out, DIM,
                           hs, DIM, nullptr, 0, NTOK, DIM, DIM, 0, 0);

    // 6. LN2 on h
    ln_kernel<<<NTOK, 256>>>(out, ln2w, ln2b, p_ln);

    // 7. Gate -> dense combine weights [T, E]
    gate_kernel<<<NTOK, 128>>>(p_ln, wg, p_comb);

    // 8. Experts: hmid = gelu(x@we1+be1); out += comb[:,e] * (hmid@we2+be2)
    for (int e = 0; e < NE; e++) {
        const float* w1 = we1 + (size_t)e * DIM * IDIM;
        const float* b1 = be1 + (size_t)e * IDIM;
        const float* w2 = we2 + (size_t)e * IDIM * DIM;
        const float* b2 = be2 + (size_t)e * DIM;
        gemm_nn<<<gBig, 256>>>(p_ln, DIM, w1, IDIM, b1, p_q, IDIM,
                               nullptr, 0, nullptr, 0, NTOK, IDIM, DIM, 1, 0);
        gemm_nn<<<gBig, 256>>>(p_q, IDIM, w2, DIM, b2, out, DIM,
                               nullptr, 0, p_comb + e, NE, NTOK, DIM, IDIM, 0, 1);
    }
}

// round 3
// speedup vs baseline: 2.0896x; 2.0896x over previous
#include <cuda_runtime.h>
#include <math.h>
#include <stdint.h>

#define BATCH 2
#define SEQ   2048
#define DIM   2048
#define NH    16
#define HDIM  128
#define NE    4
#define IDIM  2048
#define NTOK  (BATCH*SEQ)   // 4096

// ---------------- scratch (static device globals; no allocation in kernel_launch) ----
__device__ float g_ln   [(size_t)NTOK*DIM];
__device__ float g_q    [(size_t)NTOK*DIM];   // also reused as MoE hmid
__device__ float g_k    [(size_t)NTOK*DIM];
__device__ float g_v    [(size_t)NTOK*DIM];
__device__ float g_attn [(size_t)NTOK*DIM];
__device__ float g_comb [(size_t)NTOK*NE];

// ---------------- LayerNorm: one block per row ----------------
__global__ void ln_kernel(const float* __restrict__ x, const float* __restrict__ w,
                          const float* __restrict__ b, float* __restrict__ y) {
    int row = blockIdx.x;
    const float* xr = x + (size_t)row * DIM;
    float* yr = y + (size_t)row * DIM;
    __shared__ float red[256];
    int tid = threadIdx.x;
    float s = 0.f;
    for (int i = tid; i < DIM; i += 256) s += xr[i];
    red[tid] = s; __syncthreads();
    for (int o = 128; o > 0; o >>= 1) { if (tid < o) red[tid] += red[tid + o]; __syncthreads(); }
    float mu = red[0] * (1.f / DIM);
    __syncthreads();
    float v = 0.f;
    for (int i = tid; i < DIM; i += 256) { float d = xr[i] - mu; v += d * d; }
    red[tid] = v; __syncthreads();
    for (int o = 128; o > 0; o >>= 1) { if (tid < o) red[tid] += red[tid + o]; __syncthreads(); }
    float inv = rsqrtf(red[0] * (1.f / DIM) + 1e-5f);
    for (int i = tid; i < DIM; i += 256) yr[i] = (xr[i] - mu) * inv * w[i] + b[i];
}

// ---------------- TF32 tensor-core GEMM --------------------------------------------
// C[M,N] = act(A[M,K] @ B[K,N] + bias) [+resid] [*rowscale], optional +=.
// Block tile 128x128, K-tile 16. 8 warps (2 M x 4 N), warp tile 64x32 of m16n8k8.
// A in smem [128][20] (stride 20 mod 32 -> conflict-free frag reads)
// B in smem [16][136] (stride 136 mod 32 = 8 -> conflict-free frag reads)
__device__ __forceinline__ uint32_t f2tf32(float x) {
    uint32_t u;
    asm("cvt.rna.tf32.f32 %0, %1;" : "=r"(u) : "f"(x));
    return u;
}

__device__ __forceinline__ void mma_tf32(float d[4], uint32_t a0, uint32_t a1,
                                         uint32_t a2, uint32_t a3,
                                         uint32_t b0, uint32_t b1) {
    asm volatile(
        "mma.sync.aligned.m16n8k8.row.col.f32.tf32.tf32.f32 "
        "{%0,%1,%2,%3}, {%4,%5,%6,%7}, {%8,%9}, {%0,%1,%2,%3};"
        : "+f"(d[0]), "+f"(d[1]), "+f"(d[2]), "+f"(d[3])
        : "r"(a0), "r"(a1), "r"(a2), "r"(a3), "r"(b0), "r"(b1));
}

__device__ __forceinline__ void epi(float v, int gm, int gn,
                                    const float* bias, int act,
                                    const float* resid, int ldr,
                                    const float* rowscale, int rss,
                                    float* C, int ldc, int accum) {
    if (bias) v += bias[gn];
    if (act) v = 0.5f * v * (1.f + erff(v * 0.70710678118654752f));
    if (resid) v += resid[(size_t)gm * ldr + gn];
    if (rowscale) v *= rowscale[(size_t)gm * rss];
    size_t o = (size_t)gm * ldc + gn;
    if (accum) C[o] += v; else C[o] = v;
}

__global__ void __launch_bounds__(256)
gemm_tf32(const float* __restrict__ A, int lda,
          const float* __restrict__ B, int ldb,
          const float* __restrict__ bias,
          float* __restrict__ C, int ldc,
          const float* __restrict__ resid, int ldr,
          const float* __restrict__ rowscale, int rss,
          int M, int N, int K, int act, int accum) {
    __shared__ float As[128][20];
    __shared__ float Bs[16][136];
    int tid = threadIdx.x;
    int row0 = blockIdx.y * 128, col0 = blockIdx.x * 128;
    int w = tid >> 5, lane = tid & 31;
    int wm = w >> 2, wn = w & 3;          // 2 (M) x 4 (N) warps
    int m_w = wm * 64, n_w = wn * 32;
    int g = lane >> 2, q = lane & 3;

    float acc[4][4][4];
#pragma unroll
    for (int i = 0; i < 4; i++)
#pragma unroll
        for (int j = 0; j < 4; j++)
#pragma unroll
            for (int r = 0; r < 4; r++) acc[i][j][r] = 0.f;

    // Global-load index mapping (2 float4 each for A and B per thread per tile)
    int a_row0 = tid >> 2,  a_c0 = (tid & 3) * 4;            // idx = tid
    int a_row1 = (tid + 256) >> 2, a_c1 = ((tid + 256) & 3) * 4;
    int b_row0 = tid >> 5,  b_c0 = (tid & 31) * 4;           // idx = tid
    int b_row1 = (tid + 256) >> 5, b_c1 = ((tid + 256) & 31) * 4;

    const float* Ap0 = A + (size_t)(row0 + a_row0) * lda + a_c0;
    const float* Ap1 = A + (size_t)(row0 + a_row1) * lda + a_c1;
    const float* Bp0 = B + (size_t)b_row0 * ldb + col0 + b_c0;
    const float* Bp1 = B + (size_t)b_row1 * ldb + col0 + b_c1;

    float4 pa0 = *(const float4*)Ap0;
    float4 pa1 = *(const float4*)Ap1;
    float4 pb0 = *(const float4*)Bp0;
    float4 pb1 = *(const float4*)Bp1;

    for (int k0 = 0; k0 < K; k0 += 16) {
        // stage current tile into smem with tf32 rounding
        As[a_row0][a_c0 + 0] = __uint_as_float(f2tf32(pa0.x));
        As[a_row0][a_c0 + 1] = __uint_as_float(f2tf32(pa0.y));
        As[a_row0][a_c0 + 2] = __uint_as_float(f2tf32(pa0.z));
        As[a_row0][a_c0 + 3] = __uint_as_float(f2tf32(pa0.w));
        As[a_row1][a_c1 + 0] = __uint_as_float(f2tf32(pa1.x));
        As[a_row1][a_c1 + 1] = __uint_as_float(f2tf32(pa1.y));
        As[a_row1][a_c1 + 2] = __uint_as_float(f2tf32(pa1.z));
        As[a_row1][a_c1 + 3] = __uint_as_float(f2tf32(pa1.w));
        Bs[b_row0][b_c0 + 0] = __uint_as_float(f2tf32(pb0.x));
        Bs[b_row0][b_c0 + 1] = __uint_as_float(f2tf32(pb0.y));
        Bs[b_row0][b_c0 + 2] = __uint_as_float(f2tf32(pb0.z));
        Bs[b_row0][b_c0 + 3] = __uint_as_float(f2tf32(pb0.w));
        Bs[b_row1][b_c1 + 0] = __uint_as_float(f2tf32(pb1.x));
        Bs[b_row1][b_c1 + 1] = __uint_as_float(f2tf32(pb1.y));
        Bs[b_row1][b_c1 + 2] = __uint_as_float(f2tf32(pb1.z));
        Bs[b_row1][b_c1 + 3] = __uint_as_float(f2tf32(pb1.w));
        __syncthreads();

        // prefetch next tile
        if (k0 + 16 < K) {
            pa0 = *(const float4*)(Ap0 + k0 + 16);
            pa1 = *(const float4*)(Ap1 + k0 + 16);
            pb0 = *(const float4*)(Bp0 + (size_t)(k0 + 16) * ldb);
            pb1 = *(const float4*)(Bp1 + (size_t)(k0 + 16) * ldb);
        }

#pragma unroll
        for (int ks = 0; ks < 2; ks++) {
            int kb = ks * 8;
            uint32_t af[4][4], bf[4][2];
#pragma unroll
            for (int i = 0; i < 4; i++) {
                int r = m_w + i * 16 + g;
                af[i][0] = __float_as_uint(As[r][kb + q]);
                af[i][1] = __float_as_uint(As[r + 8][kb + q]);
                af[i][2] = __float_as_uint(As[r][kb + q + 4]);
                af[i][3] = __float_as_uint(As[r + 8][kb + q + 4]);
            }
#pragma unroll
            for (int j = 0; j < 4; j++) {
                int c = n_w + j * 8 + g;
                bf[j][0] = __float_as_uint(Bs[kb + q][c]);
                bf[j][1] = __float_as_uint(Bs[kb + q + 4][c]);
            }
#pragma unroll
            for (int i = 0; i < 4; i++)
#pragma unroll
                for (int j = 0; j < 4; j++)
                    mma_tf32(acc[i][j], af[i][0], af[i][1], af[i][2], af[i][3],
                             bf[j][0], bf[j][1]);
        }
        __syncthreads();
    }

    // epilogue
#pragma unroll
    for (int i = 0; i < 4; i++) {
        int r0 = row0 + m_w + i * 16 + g;
#pragma unroll
        for (int j = 0; j < 4; j++) {
            int cb = col0 + n_w + j * 8 + q * 2;
            epi(acc[i][j][0], r0,     cb,     bias, act, resid, ldr, rowscale, rss, C, ldc, accum);
            epi(acc[i][j][1], r0,     cb + 1, bias, act, resid, ldr, rowscale, rss, C, ldc, accum);
            epi(acc[i][j][2], r0 + 8, cb,     bias, act, resid, ldr, rowscale, rss, C, ldc, accum);
            epi(acc[i][j][3], r0 + 8, cb + 1, bias, act, resid, ldr, rowscale, rss, C, ldc, accum);
        }
    }
}

// ---------------- RoPE in-place on Q and K (double-precision trig; fast-math-proof) ----
__global__ void rope_kernel(float* __restrict__ q, float* __restrict__ k) {
    int idx = blockIdx.x * blockDim.x + threadIdx.x;   // over NTOK*NH*64
    if (idx >= NTOK * NH * 64) return;
    int i = idx & 63;
    int rem = idx >> 6;
    int h = rem % NH;
    int t = rem / NH;
    int s = t % SEQ;
    float invf = (float)(1.0 / pow(10000.0, (double)i / 64.0));
    float ang = (float)s * invf;              // fp32 angle, like the reference
    double angd = (double)ang;
    float c  = (float)cos(angd);              // exact trig of that fp32 angle
    float sn = (float)sin(angd);
    size_t base = (size_t)t * DIM + (size_t)h * HDIM;
    float q1 = q[base + i], q2 = q[base + 64 + i];
    q[base + i]      = q1 * c - q2 * sn;
    q[base + 64 + i] = q2 * c + q1 * sn;
    float k1 = k[base + i], k2 = k[base + 64 + i];
    k[base + i]      = k1 * c - k2 * sn;
    k[base + 64 + i] = k2 * c + k1 * sn;
}

// ---------------- Fused causal attention: one warp per (b, h, query row) --------------
__global__ void attn_kernel(const float* __restrict__ q, const float* __restrict__ k,
                            const float* __restrict__ v, float* __restrict__ attn) {
    int gw = (blockIdx.x * blockDim.x + threadIdx.x) >> 5;   // global warp id
    int lane = threadIdx.x & 31;
    if (gw >= BATCH * NH * SEQ) return;
    int qpos = gw % SEQ;
    int h = (gw / SEQ) % NH;
    int b = gw / (SEQ * NH);
    const float alpha = 0.08838834764831845f;   // 1/sqrt(128)

    const float4* q4 = (const float4*)(q + ((size_t)(b * SEQ + qpos)) * DIM + h * HDIM);
    float4 qv = q4[lane];

    float m = -3.0e38f, l = 0.f;
    float4 acc = make_float4(0.f, 0.f, 0.f, 0.f);

    const float* kbase = k + ((size_t)b * SEQ) * DIM + h * HDIM;
    const float* vbase = v + ((size_t)b * SEQ) * DIM + h * HDIM;

    for (int kp = 0; kp <= qpos; kp++) {
        const float4* k4 = (const float4*)(kbase + (size_t)kp * DIM);
        float4 kk = k4[lane];
        float s = qv.x * kk.x + qv.y * kk.y + qv.z * kk.z + qv.w * kk.w;
#pragma unroll
        for (int off = 16; off > 0; off >>= 1)
            s += __shfl_xor_sync(0xffffffffu, s, off);
        s *= alpha;
        float mn = fmaxf(m, s);
        float corr = expf(m - mn);
        float p = expf(s - mn);
        l = l * corr + p;
        const float4* v4 = (const float4*)(vbase + (size_t)kp * DIM);
        float4 vv = v4[lane];
        acc.x = acc.x * corr + p * vv.x;
        acc.y = acc.y * corr + p * vv.y;
        acc.z = acc.z * corr + p * vv.z;
        acc.w = acc.w * corr + p * vv.w;
        m = mn;
    }
    float invl = 1.f / l;
    float4* o4 = (float4*)(attn + ((size_t)(b * SEQ + qpos)) * DIM + h * HDIM);
    o4[lane] = make_float4(acc.x * invl, acc.y * invl, acc.z * invl, acc.w * invl);
}

// ---------------- MoE gate: softmax -> top2 -> renormalized softmax --------------------
__global__ void gate_kernel(const float* __restrict__ x, const float* __restrict__ wg,
                            float* __restrict__ comb) {
    int t = blockIdx.x;
    int tid = threadIdx.x;
    __shared__ float red[NE * 128];
    const float* xr = x + (size_t)t * DIM;
    float acc[NE] = {0.f, 0.f, 0.f, 0.f};
    for (int d = tid; d < DIM; d += 128) {
        float xv = xr[d];
#pragma unroll
        for (int e = 0; e < NE; e++) acc[e] += xv * wg[(size_t)d * NE + e];
    }
#pragma unroll
    for (int e = 0; e < NE; e++) red[e * 128 + tid] = acc[e];
    __syncthreads();
    for (int o = 64; o > 0; o >>= 1) {
        if (tid < o) {
#pragma unroll
            for (int e = 0; e < NE; e++) red[e * 128 + tid] += red[e * 128 + tid + o];
        }
        __syncthreads();
    }
    if (tid == 0) {
        float l[NE];
#pragma unroll
        for (int e = 0; e < NE; e++) l[e] = red[e * 128];
        float mx = fmaxf(fmaxf(l[0], l[1]), fmaxf(l[2], l[3]));
        float ex[NE], s = 0.f;
#pragma unroll
        for (int e = 0; e < NE; e++) { ex[e] = expf(l[e] - mx); s += ex[e]; }
        float p[NE];
#pragma unroll
        for (int e = 0; e < NE; e++) p[e] = ex[e] / s;
        int i0 = 0;
#pragma unroll
        for (int e = 1; e < NE; e++) if (p[e] > p[i0]) i0 = e;
        int i1 = (i0 == 0) ? 1 : 0;
#pragma unroll
        for (int e = 0; e < NE; e++) if (e != i0 && p[e] > p[i1]) i1 = e;
        float e1 = expf(p[i1] - p[i0]);     // softmax over the two top probabilities
        float invs = 1.f / (1.f + e1);
        float c[NE] = {0.f, 0.f, 0.f, 0.f};
        c[i0] = invs;
        c[i1] = e1 * invs;
#pragma unroll
        for (int e = 0; e < NE; e++) comb[(size_t)t * NE + e] = c[e];
    }
}

// ---------------- host orchestration ---------------------------------------------------
extern "C" void kernel_launch(void* const* d_in, const int* in_sizes, int n_in,
                              void* d_out, int out_size) {
    (void)in_sizes; (void)n_in; (void)out_size;
    const float* hs   = (const float*)d_in[0];
    const float* wq   = (const float*)d_in[1];
    const float* bq   = (const float*)d_in[2];
    const float* wk   = (const float*)d_in[3];
    const float* bk   = (const float*)d_in[4];
    const float* wv   = (const float*)d_in[5];
    const float* bv   = (const float*)d_in[6];
    const float* wo   = (const float*)d_in[7];
    const float* bo   = (const float*)d_in[8];
    const float* ln1w = (const float*)d_in[9];
    const float* ln1b = (const float*)d_in[10];
    const float* ln2w = (const float*)d_in[11];
    const float* ln2b = (const float*)d_in[12];
    const float* wg   = (const float*)d_in[13];
    const float* we1  = (const float*)d_in[14];
    const float* be1  = (const float*)d_in[15];
    const float* we2  = (const float*)d_in[16];
    const float* be2  = (const float*)d_in[17];
    float* out = (float*)d_out;

    float *p_ln, *p_q, *p_k, *p_v, *p_attn, *p_comb;
    cudaGetSymbolAddress((void**)&p_ln, g_ln);
    cudaGetSymbolAddress((void**)&p_q, g_q);
    cudaGetSymbolAddress((void**)&p_k, g_k);
    cudaGetSymbolAddress((void**)&p_v, g_v);
    cudaGetSymbolAddress((void**)&p_attn, g_attn);
    cudaGetSymbolAddress((void**)&p_comb, g_comb);

    // 1. LN1
    ln_kernel<<<NTOK, 256>>>(hs, ln1w, ln1b, p_ln);

    // 2. QKV projections (TF32 tensor cores)
    dim3 gBig(DIM / 128, NTOK / 128);
    gemm_tf32<<<gBig, 256>>>(p_ln, DIM, wq, DIM, bq, p_q, DIM,
                             nullptr, 0, nullptr, 0, NTOK, DIM, DIM, 0, 0);
    gemm_tf32<<<gBig, 256>>>(p_ln, DIM, wk, DIM, bk, p_k, DIM,
                             nullptr, 0, nullptr, 0, NTOK, DIM, DIM, 0, 0);
    gemm_tf32<<<gBig, 256>>>(p_ln, DIM, wv, DIM, bv, p_v, DIM,
                             nullptr, 0, nullptr, 0, NTOK, DIM, DIM, 0, 0);

    // 3. RoPE on Q,K
    int nrope = NTOK * NH * 64;
    rope_kernel<<<(nrope + 255) / 256, 256>>>(p_q, p_k);

    // 4. Fused causal attention
    int nwarps = BATCH * NH * SEQ;
    attn_kernel<<<(nwarps * 32) / 256, 256>>>(p_q, p_k, p_v, p_attn);

    // 5. O-proj + bias + residual(hidden) -> out  (= h)
    gemm_tf32<<<gBig, 256>>>(p_attn, DIM, wo, DIM, bo, out, DIM,
                             hs, DIM, nullptr, 0, NTOK, DIM, DIM, 0, 0);

    // 6. LN2 on h
    ln_kernel<<<NTOK, 256>>>(out, ln2w, ln2b, p_ln);

    // 7. Gate -> dense combine weights [T, E]
    gate_kernel<<<NTOK, 128>>>(p_ln, wg, p_comb);

    // 8. Experts: hmid = gelu(x@we1+be1); out += comb[:,e] * (hmid@we2+be2)
    for (int e = 0; e < NE; e++) {
        const float* w1 = we1 + (size_t)e * DIM * IDIM;
        const float* b1 = be1 + (size_t)e * IDIM;
        const float* w2 = we2 + (size_t)e * IDIM * DIM;
        const float* b2 = be2 + (size_t)e * DIM;
        gemm_tf32<<<gBig, 256>>>(p_ln, DIM, w1, IDIM, b1, p_q, IDIM,
                                 nullptr, 0, nullptr, 0, NTOK, IDIM, DIM, 1, 0);
        gemm_tf32<<<gBig, 256>>>(p_q, IDIM, w2, DIM, b2, out, DIM,
                                 nullptr, 0, p_comb + e, NE, NTOK, DIM, IDIM, 0, 1);
    }
}

// round 6
// speedup vs baseline: 4.3532x; 2.0832x over previous
#include <cuda_runtime.h>
#include <cuda_bf16.h>
#include <math.h>
#include <stdint.h>

#define BATCH 2
#define SEQ   2048
#define DIM   2048
#define NH    16
#define HDIM  128
#define NE    4
#define IDIM  2048
#define NTOK  (BATCH*SEQ)   // 4096

// ---------------- scratch (static device globals) ----
__device__ float g_ln   [(size_t)NTOK*DIM];
__device__ float g_q    [(size_t)NTOK*DIM];   // also reused as MoE hmid
__device__ float g_k    [(size_t)NTOK*DIM];
__device__ float g_v    [(size_t)NTOK*DIM];
__device__ float g_attn [(size_t)NTOK*DIM];
__device__ float g_comb [(size_t)NTOK*NE];

__device__ __forceinline__ uint32_t f2tf32(float x) {
    uint32_t u;
    asm("cvt.rna.tf32.f32 %0, %1;" : "=r"(u) : "f"(x));
    return u;
}
__device__ __forceinline__ float tf32r(float x) { return __uint_as_float(f2tf32(x)); }

__device__ __forceinline__ void mma_tf32(float d[4], uint32_t a0, uint32_t a1,
                                         uint32_t a2, uint32_t a3,
                                         uint32_t b0, uint32_t b1) {
    asm volatile(
        "mma.sync.aligned.m16n8k8.row.col.f32.tf32.tf32.f32 "
        "{%0,%1,%2,%3}, {%4,%5,%6,%7}, {%8,%9}, {%0,%1,%2,%3};"
        : "+f"(d[0]), "+f"(d[1]), "+f"(d[2]), "+f"(d[3])
        : "r"(a0), "r"(a1), "r"(a2), "r"(a3), "r"(b0), "r"(b1));
}

__device__ __forceinline__ void mma_bf16(float d[4], uint32_t a0, uint32_t a1,
                                         uint32_t a2, uint32_t a3,
                                         uint32_t b0, uint32_t b1) {
    asm volatile(
        "mma.sync.aligned.m16n8k16.row.col.f32.bf16.bf16.f32 "
        "{%0,%1,%2,%3}, {%4,%5,%6,%7}, {%8,%9}, {%0,%1,%2,%3};"
        : "+f"(d[0]), "+f"(d[1]), "+f"(d[2]), "+f"(d[3])
        : "r"(a0), "r"(a1), "r"(a2), "r"(a3), "r"(b0), "r"(b1));
}

__device__ __forceinline__ uint32_t pack_bf2(float lo, float hi) {
    __nv_bfloat162 t = __floats2bfloat162_rn(lo, hi);   // .x = lo (low half)
    return *(uint32_t*)&t;
}
__device__ __forceinline__ uint16_t bf16bits(float x) {
    __nv_bfloat16 t = __float2bfloat16_rn(x);
    return *(uint16_t*)&t;
}

// ---------------- LayerNorm ----------------
__global__ void ln_kernel(const float* __restrict__ x, const float* __restrict__ w,
                          const float* __restrict__ b, float* __restrict__ y) {
    int row = blockIdx.x;
    const float* xr = x + (size_t)row * DIM;
    float* yr = y + (size_t)row * DIM;
    __shared__ float red[256];
    int tid = threadIdx.x;
    float s = 0.f;
    for (int i = tid; i < DIM; i += 256) s += xr[i];
    red[tid] = s; __syncthreads();
    for (int o = 128; o > 0; o >>= 1) { if (tid < o) red[tid] += red[tid + o]; __syncthreads(); }
    float mu = red[0] * (1.f / DIM);
    __syncthreads();
    float v = 0.f;
    for (int i = tid; i < DIM; i += 256) { float d = xr[i] - mu; v += d * d; }
    red[tid] = v; __syncthreads();
    for (int o = 128; o > 0; o >>= 1) { if (tid < o) red[tid] += red[tid + o]; __syncthreads(); }
    float inv = rsqrtf(red[0] * (1.f / DIM) + 1e-5f);
    for (int i = tid; i < DIM; i += 256) yr[i] = (xr[i] - mu) * inv * w[i] + b[i];
}

// ---------------- TF32 tensor-core GEMM (R2, proven) --------------------------------
__device__ __forceinline__ void epi(float v, int gm, int gn,
                                    const float* bias, int act,
                                    const float* resid, int ldr,
                                    const float* rowscale, int rss,
                                    float* C, int ldc, int accum) {
    if (bias) v += bias[gn];
    if (act) v = 0.5f * v * (1.f + erff(v * 0.70710678118654752f));
    if (resid) v += resid[(size_t)gm * ldr + gn];
    if (rowscale) v *= rowscale[(size_t)gm * rss];
    size_t o = (size_t)gm * ldc + gn;
    if (accum) C[o] += v; else C[o] = v;
}

__global__ void __launch_bounds__(256)
gemm_tf32(const float* __restrict__ A, int lda,
          const float* __restrict__ B, int ldb,
          const float* __restrict__ bias,
          float* __restrict__ C, int ldc,
          const float* __restrict__ resid, int ldr,
          const float* __restrict__ rowscale, int rss,
          int M, int N, int K, int act, int accum) {
    __shared__ float As[128][20];
    __shared__ float Bs[16][136];
    int tid = threadIdx.x;
    int row0 = blockIdx.y * 128, col0 = blockIdx.x * 128;
    int w = tid >> 5, lane = tid & 31;
    int wm = w >> 2, wn = w & 3;
    int m_w = wm * 64, n_w = wn * 32;
    int g = lane >> 2, q = lane & 3;

    float acc[4][4][4];
#pragma unroll
    for (int i = 0; i < 4; i++)
#pragma unroll
        for (int j = 0; j < 4; j++)
#pragma unroll
            for (int r = 0; r < 4; r++) acc[i][j][r] = 0.f;

    int a_row0 = tid >> 2,  a_c0 = (tid & 3) * 4;
    int a_row1 = (tid + 256) >> 2, a_c1 = ((tid + 256) & 3) * 4;
    int b_row0 = tid >> 5,  b_c0 = (tid & 31) * 4;
    int b_row1 = (tid + 256) >> 5, b_c1 = ((tid + 256) & 31) * 4;

    const float* Ap0 = A + (size_t)(row0 + a_row0) * lda + a_c0;
    const float* Ap1 = A + (size_t)(row0 + a_row1) * lda + a_c1;
    const float* Bp0 = B + (size_t)b_row0 * ldb + col0 + b_c0;
    const float* Bp1 = B + (size_t)b_row1 * ldb + col0 + b_c1;

    float4 pa0 = *(const float4*)Ap0;
    float4 pa1 = *(const float4*)Ap1;
    float4 pb0 = *(const float4*)Bp0;
    float4 pb1 = *(const float4*)Bp1;

    for (int k0 = 0; k0 < K; k0 += 16) {
        As[a_row0][a_c0 + 0] = tf32r(pa0.x);
        As[a_row0][a_c0 + 1] = tf32r(pa0.y);
        As[a_row0][a_c0 + 2] = tf32r(pa0.z);
        As[a_row0][a_c0 + 3] = tf32r(pa0.w);
        As[a_row1][a_c1 + 0] = tf32r(pa1.x);
        As[a_row1][a_c1 + 1] = tf32r(pa1.y);
        As[a_row1][a_c1 + 2] = tf32r(pa1.z);
        As[a_row1][a_c1 + 3] = tf32r(pa1.w);
        Bs[b_row0][b_c0 + 0] = tf32r(pb0.x);
        Bs[b_row0][b_c0 + 1] = tf32r(pb0.y);
        Bs[b_row0][b_c0 + 2] = tf32r(pb0.z);
        Bs[b_row0][b_c0 + 3] = tf32r(pb0.w);
        Bs[b_row1][b_c1 + 0] = tf32r(pb1.x);
        Bs[b_row1][b_c1 + 1] = tf32r(pb1.y);
        Bs[b_row1][b_c1 + 2] = tf32r(pb1.z);
        Bs[b_row1][b_c1 + 3] = tf32r(pb1.w);
        __syncthreads();

        if (k0 + 16 < K) {
            pa0 = *(const float4*)(Ap0 + k0 + 16);
            pa1 = *(const float4*)(Ap1 + k0 + 16);
            pb0 = *(const float4*)(Bp0 + (size_t)(k0 + 16) * ldb);
            pb1 = *(const float4*)(Bp1 + (size_t)(k0 + 16) * ldb);
        }

#pragma unroll
        for (int ks = 0; ks < 2; ks++) {
            int kb = ks * 8;
            uint32_t af[4][4], bf[4][2];
#pragma unroll
            for (int i = 0; i < 4; i++) {
                int r = m_w + i * 16 + g;
                af[i][0] = __float_as_uint(As[r][kb + q]);
                af[i][1] = __float_as_uint(As[r + 8][kb + q]);
                af[i][2] = __float_as_uint(As[r][kb + q + 4]);
                af[i][3] = __float_as_uint(As[r + 8][kb + q + 4]);
            }
#pragma unroll
            for (int j = 0; j < 4; j++) {
                int c = n_w + j * 8 + g;
                bf[j][0] = __float_as_uint(Bs[kb + q][c]);
                bf[j][1] = __float_as_uint(Bs[kb + q + 4][c]);
            }
#pragma unroll
            for (int i = 0; i < 4; i++)
#pragma unroll
                for (int j = 0; j < 4; j++)
                    mma_tf32(acc[i][j], af[i][0], af[i][1], af[i][2], af[i][3],
                             bf[j][0], bf[j][1]);
        }
        __syncthreads();
    }

#pragma unroll
    for (int i = 0; i < 4; i++) {
        int r0 = row0 + m_w + i * 16 + g;
#pragma unroll
        for (int j = 0; j < 4; j++) {
            int cb = col0 + n_w + j * 8 + q * 2;
            epi(acc[i][j][0], r0,     cb,     bias, act, resid, ldr, rowscale, rss, C, ldc, accum);
            epi(acc[i][j][1], r0,     cb + 1, bias, act, resid, ldr, rowscale, rss, C, ldc, accum);
            epi(acc[i][j][2], r0 + 8, cb,     bias, act, resid, ldr, rowscale, rss, C, ldc, accum);
            epi(acc[i][j][3], r0 + 8, cb + 1, bias, act, resid, ldr, rowscale, rss, C, ldc, accum);
        }
    }
}

// ---------------- RoPE ----------------------------------------------------------------
__global__ void rope_kernel(float* __restrict__ q, float* __restrict__ k) {
    int idx = blockIdx.x * blockDim.x + threadIdx.x;
    if (idx >= NTOK * NH * 64) return;
    int i = idx & 63;
    int rem = idx >> 6;
    int h = rem % NH;
    int t = rem / NH;
    int s = t % SEQ;
    float invf = (float)(1.0 / pow(10000.0, (double)i / 64.0));
    float ang = (float)s * invf;
    double angd = (double)ang;
    float c  = (float)cos(angd);
    float sn = (float)sin(angd);
    size_t base = (size_t)t * DIM + (size_t)h * HDIM;
    float q1 = q[base + i], q2 = q[base + 64 + i];
    q[base + i]      = q1 * c - q2 * sn;
    q[base + 64 + i] = q2 * c + q1 * sn;
    float k1 = k[base + i], k2 = k[base + 64 + i];
    k[base + i]      = k1 * c - k2 * sn;
    k[base + 64 + i] = k2 * c + k1 * sn;
}

// ---------------- Flash attention, bf16 MMA, static smem, 128 threads = 4 warps --------
// Each block: 64 queries of one (b,h); warp w owns rows [w*16, w*16+16). K-tiles of 32.
__global__ void __launch_bounds__(128)
fa_kernel(const float* __restrict__ q, const float* __restrict__ k,
          const float* __restrict__ v, float* __restrict__ attn) {
    __shared__ uint32_t Qs[64][68];    // [query][dim-pair]   17408 B
    __shared__ uint32_t Ks[32][68];    // [key][dim-pair]      8704 B
    __shared__ uint32_t Vt[128][20];   // [dim][key-pair]     10240 B
    __shared__ uint32_t Ps[4][16][20]; // per-warp [row][key-pair] 5120 B

    int bh = blockIdx.y;
    int b = bh / NH, h = bh % NH;
    int q0 = blockIdx.x * 64;
    int tid = threadIdx.x, w = tid >> 5, lane = tid & 31;   // w in 0..3
    int g = lane >> 2, qd = lane & 3;
    const float alpha = 0.08838834764831845f;   // 1/sqrt(128)

    const float* qb = q + ((size_t)b * SEQ) * DIM + h * HDIM;
    const float* kb_ = k + ((size_t)b * SEQ) * DIM + h * HDIM;
    const float* vb = v + ((size_t)b * SEQ) * DIM + h * HDIM;

    // stage Q tile (alpha folded in before bf16 rounding)
    for (int i = tid; i < 64 * 32; i += 128) {   // float4 chunks: row=i>>5, c4=i&31
        int r = i >> 5, c4 = i & 31;
        float4 t = *(const float4*)(qb + (size_t)(q0 + r) * DIM + c4 * 4);
        Qs[r][c4 * 2]     = pack_bf2(t.x * alpha, t.y * alpha);
        Qs[r][c4 * 2 + 1] = pack_bf2(t.z * alpha, t.w * alpha);
    }

    float m0 = -1e30f, m1 = -1e30f, l0 = 0.f, l1 = 0.f;
    float out[16][4];
#pragma unroll
    for (int i = 0; i < 16; i++)
#pragma unroll
        for (int r = 0; r < 4; r++) out[i][r] = 0.f;

    int ktiles = q0 / 32 + 2;

    for (int kt = 0; kt < ktiles; kt++) {
        int k0 = kt * 32;
        __syncthreads();   // prior reads of Ks/Vt done (and Q staged on iter 0)
        // stage K tile (pairs) and V tile (transposed scalars)
        for (int i = tid; i < 32 * 32; i += 128) {
            int r = i >> 5, c4 = i & 31;
            float4 tk = *(const float4*)(kb_ + (size_t)(k0 + r) * DIM + c4 * 4);
            Ks[r][c4 * 2]     = pack_bf2(tk.x, tk.y);
            Ks[r][c4 * 2 + 1] = pack_bf2(tk.z, tk.w);
            float4 tv = *(const float4*)(vb + (size_t)(k0 + r) * DIM + c4 * 4);
            uint16_t* vt = (uint16_t*)Vt;     // row stride = 40 uint16
            vt[(c4 * 4 + 0) * 40 + r] = bf16bits(tv.x);
            vt[(c4 * 4 + 1) * 40 + r] = bf16bits(tv.y);
            vt[(c4 * 4 + 2) * 40 + r] = bf16bits(tv.z);
            vt[(c4 * 4 + 3) * 40 + r] = bf16bits(tv.w);
        }
        __syncthreads();

        // scores: S(16x32) = Qw(16x128) @ K^T(128x32)
        float sc[4][4];
#pragma unroll
        for (int nt = 0; nt < 4; nt++)
#pragma unroll
            for (int r = 0; r < 4; r++) sc[nt][r] = 0.f;
#pragma unroll
        for (int ks = 0; ks < 8; ks++) {      // 8 k16-steps over HDIM
            int kp = ks * 8;
            uint32_t a0 = Qs[w * 16 + g][kp + qd];
            uint32_t a1 = Qs[w * 16 + g + 8][kp + qd];
            uint32_t a2 = Qs[w * 16 + g][kp + qd + 4];
            uint32_t a3 = Qs[w * 16 + g + 8][kp + qd + 4];
#pragma unroll
            for (int nt = 0; nt < 4; nt++) {
                uint32_t b0 = Ks[nt * 8 + g][kp + qd];
                uint32_t b1 = Ks[nt * 8 + g][kp + qd + 4];
                mma_bf16(sc[nt], a0, a1, a2, a3, b0, b1);
            }
        }

        // causal mask (only tiles that can cross the diagonal)
        if (k0 + 31 > q0) {
            int rq0 = q0 + w * 16 + g;
            int rq1 = rq0 + 8;
#pragma unroll
            for (int nt = 0; nt < 4; nt++) {
                int kc = k0 + nt * 8 + qd * 2;
                if (kc     > rq0) sc[nt][0] = -1e30f;
                if (kc + 1 > rq0) sc[nt][1] = -1e30f;
                if (kc     > rq1) sc[nt][2] = -1e30f;
                if (kc + 1 > rq1) sc[nt][3] = -1e30f;
            }
        }

        // online softmax update (rows rq0, rq1; reduce across the 4 lanes of each row)
        float tm0 = -1e30f, tm1 = -1e30f;
#pragma unroll
        for (int nt = 0; nt < 4; nt++) {
            tm0 = fmaxf(tm0, fmaxf(sc[nt][0], sc[nt][1]));
            tm1 = fmaxf(tm1, fmaxf(sc[nt][2], sc[nt][3]));
        }
        tm0 = fmaxf(tm0, __shfl_xor_sync(0xffffffffu, tm0, 1));
        tm0 = fmaxf(tm0, __shfl_xor_sync(0xffffffffu, tm0, 2));
        tm1 = fmaxf(tm1, __shfl_xor_sync(0xffffffffu, tm1, 1));
        tm1 = fmaxf(tm1, __shfl_xor_sync(0xffffffffu, tm1, 2));

        float mn0 = fmaxf(m0, tm0), mn1 = fmaxf(m1, tm1);
        float corr0 = expf(m0 - mn0), corr1 = expf(m1 - mn1);
        m0 = mn0; m1 = mn1;
        l0 *= corr0; l1 *= corr1;
#pragma unroll
        for (int nt = 0; nt < 16; nt++) {
            out[nt][0] *= corr0; out[nt][1] *= corr0;
            out[nt][2] *= corr1; out[nt][3] *= corr1;
        }

        float s0 = 0.f, s1 = 0.f;
#pragma unroll
        for (int nt = 0; nt < 4; nt++) {
            float p0 = expf(sc[nt][0] - m0);
            float p1 = expf(sc[nt][1] - m0);
            float p2 = expf(sc[nt][2] - m1);
            float p3 = expf(sc[nt][3] - m1);
            s0 += p0 + p1; s1 += p2 + p3;
            Ps[w][g][nt * 4 + qd]     = pack_bf2(p0, p1);
            Ps[w][g + 8][nt * 4 + qd] = pack_bf2(p2, p3);
        }
        s0 += __shfl_xor_sync(0xffffffffu, s0, 1);
        s0 += __shfl_xor_sync(0xffffffffu, s0, 2);
        s1 += __shfl_xor_sync(0xffffffffu, s1, 1);
        s1 += __shfl_xor_sync(0xffffffffu, s1, 2);
        l0 += s0; l1 += s1;
        __syncwarp();

        // out(16x128) += P(16x32) @ V(32x128)
#pragma unroll
        for (int ks = 0; ks < 2; ks++) {
            int kp = ks * 8;
            uint32_t a0 = Ps[w][g][kp + qd];
            uint32_t a1 = Ps[w][g + 8][kp + qd];
            uint32_t a2 = Ps[w][g][kp + qd + 4];
            uint32_t a3 = Ps[w][g + 8][kp + qd + 4];
#pragma unroll
            for (int nt = 0; nt < 16; nt++) {
                uint32_t b0 = Vt[nt * 8 + g][kp + qd];
                uint32_t b1 = Vt[nt * 8 + g][kp + qd + 4];
                mma_bf16(out[nt], a0, a1, a2, a3, b0, b1);
            }
        }
        __syncwarp();
    }

    float inv0 = 1.f / l0, inv1 = 1.f / l1;
    int r0g = q0 + w * 16 + g;
    float* ob = attn + ((size_t)b * SEQ) * DIM + h * HDIM;
#pragma unroll
    for (int nt = 0; nt < 16; nt++) {
        int c = nt * 8 + qd * 2;
        *(float2*)(ob + (size_t)r0g * DIM + c) =
            make_float2(out[nt][0] * inv0, out[nt][1] * inv0);
        *(float2*)(ob + (size_t)(r0g + 8) * DIM + c) =
            make_float2(out[nt][2] * inv1, out[nt][3] * inv1);
    }
}

// ---------------- MoE gate -------------------------------------------------------------
__global__ void gate_kernel(const float* __restrict__ x, const float* __restrict__ wg,
                            float* __restrict__ comb) {
    int t = blockIdx.x;
    int tid = threadIdx.x;
    __shared__ float red[NE * 128];
    const float* xr = x + (size_t)t * DIM;
    float acc[NE] = {0.f, 0.f, 0.f, 0.f};
    for (int d = tid; d < DIM; d += 128) {
        float xv = xr[d];
#pragma unroll
        for (int e = 0; e < NE; e++) acc[e] += xv * wg[(size_t)d * NE + e];
    }
#pragma unroll
    for (int e = 0; e < NE; e++) red[e * 128 + tid] = acc[e];
    __syncthreads();
    for (int o = 64; o > 0; o >>= 1) {
        if (tid < o) {
#pragma unroll
            for (int e = 0; e < NE; e++) red[e * 128 + tid] += red[e * 128 + tid + o];
        }
        __syncthreads();
    }
    if (tid == 0) {
        float l[NE];
#pragma unroll
        for (int e = 0; e < NE; e++) l[e] = red[e * 128];
        float mx = fmaxf(fmaxf(l[0], l[1]), fmaxf(l[2], l[3]));
        float ex[NE], s = 0.f;
#pragma unroll
        for (int e = 0; e < NE; e++) { ex[e] = expf(l[e] - mx); s += ex[e]; }
        float p[NE];
#pragma unroll
        for (int e = 0; e < NE; e++) p[e] = ex[e] / s;
        int i0 = 0;
#pragma unroll
        for (int e = 1; e < NE; e++) if (p[e] > p[i0]) i0 = e;
        int i1 = (i0 == 0) ? 1 : 0;
#pragma unroll
        for (int e = 0; e < NE; e++) if (e != i0 && p[e] > p[i1]) i1 = e;
        float e1 = expf(p[i1] - p[i0]);
        float invs = 1.f / (1.f + e1);
        float c[NE] = {0.f, 0.f, 0.f, 0.f};
        c[i0] = invs;
        c[i1] = e1 * invs;
#pragma unroll
        for (int e = 0; e < NE; e++) comb[(size_t)t * NE + e] = c[e];
    }
}

// ---------------- host orchestration ---------------------------------------------------
extern "C" void kernel_launch(void* const* d_in, const int* in_sizes, int n_in,
                              void* d_out, int out_size) {
    (void)in_sizes; (void)n_in; (void)out_size;
    const float* hs   = (const float*)d_in[0];
    const float* wq   = (const float*)d_in[1];
    const float* bq   = (const float*)d_in[2];
    const float* wk   = (const float*)d_in[3];
    const float* bk   = (const float*)d_in[4];
    const float* wv   = (const float*)d_in[5];
    const float* bv   = (const float*)d_in[6];
    const float* wo   = (const float*)d_in[7];
    const float* bo   = (const float*)d_in[8];
    const float* ln1w = (const float*)d_in[9];
    const float* ln1b = (const float*)d_in[10];
    const float* ln2w = (const float*)d_in[11];
    const float* ln2b = (const float*)d_in[12];
    const float* wg   = (const float*)d_in[13];
    const float* we1  = (const float*)d_in[14];
    const float* be1  = (const float*)d_in[15];
    const float* we2  = (const float*)d_in[16];
    const float* be2  = (const float*)d_in[17];
    float* out = (float*)d_out;

    float *p_ln, *p_q, *p_k, *p_v, *p_attn, *p_comb;
    cudaGetSymbolAddress((void**)&p_ln, g_ln);
    cudaGetSymbolAddress((void**)&p_q, g_q);
    cudaGetSymbolAddress((void**)&p_k, g_k);
    cudaGetSymbolAddress((void**)&p_v, g_v);
    cudaGetSymbolAddress((void**)&p_attn, g_attn);
    cudaGetSymbolAddress((void**)&p_comb, g_comb);

    // 1. LN1
    ln_kernel<<<NTOK, 256>>>(hs, ln1w, ln1b, p_ln);

    // 2. QKV projections (TF32 tensor cores)
    dim3 gBig(DIM / 128, NTOK / 128);
    gemm_tf32<<<gBig, 256>>>(p_ln, DIM, wq, DIM, bq, p_q, DIM,
                             nullptr, 0, nullptr, 0, NTOK, DIM, DIM, 0, 0);
    gemm_tf32<<<gBig, 256>>>(p_ln, DIM, wk, DIM, bk, p_k, DIM,
                             nullptr, 0, nullptr, 0, NTOK, DIM, DIM, 0, 0);
    gemm_tf32<<<gBig, 256>>>(p_ln, DIM, wv, DIM, bv, p_v, DIM,
                             nullptr, 0, nullptr, 0, NTOK, DIM, DIM, 0, 0);

    // 3. RoPE on Q,K
    int nrope = NTOK * NH * 64;
    rope_kernel<<<(nrope + 255) / 256, 256>>>(p_q, p_k);

    // 4. Flash attention (bf16 MMA, 4 warps = 128 threads per block)
    dim3 gFA(SEQ / 64, BATCH * NH);
    fa_kernel<<<gFA, 128>>>(p_q, p_k, p_v, p_attn);

    // 5. O-proj + bias + residual(hidden) -> out  (= h)
    gemm_tf32<<<gBig, 256>>>(p_attn, DIM, wo, DIM, bo, out, DIM,
                             hs, DIM, nullptr, 0, NTOK, DIM, DIM, 0, 0);

    // 6. LN2 on h
    ln_kernel<<<NTOK, 256>>>(out, ln2w, ln2b, p_ln);

    // 7. Gate -> dense combine weights [T, E]
    gate_kernel<<<NTOK, 128>>>(p_ln, wg, p_comb);

    // 8. Experts
    for (int e = 0; e < NE; e++) {
        const float* w1 = we1 + (size_t)e * DIM * IDIM;
        const float* b1 = be1 + (size_t)e * IDIM;
        const float* w2 = we2 + (size_t)e * IDIM * DIM;
        const float* b2 = be2 + (size_t)e * DIM;
        gemm_tf32<<<gBig, 256>>>(p_ln, DIM, w1, IDIM, b1, p_q, IDIM,
                                 nullptr, 0, nullptr, 0, NTOK, IDIM, DIM, 1, 0);
        gemm_tf32<<<gBig, 256>>>(p_q, IDIM, w2, DIM, b2, out, DIM,
                                 nullptr, 0, p_comb + e, NE, NTOK, DIM, IDIM, 0, 1);
    }
}

// round 7
// speedup vs baseline: 5.5290x; 1.2701x over previous
#include <cuda_runtime.h>
#include <cuda_bf16.h>
#include <math.h>
#include <stdint.h>

#define BATCH 2
#define SEQ   2048
#define DIM   2048
#define NH    16
#define HDIM  128
#define NE    4
#define IDIM  2048
#define NTOK  (BATCH*SEQ)   // 4096

// ---------------- scratch (static device globals) ----
__device__ float g_ln   [(size_t)NTOK*DIM];
__device__ float g_q    [(size_t)NTOK*DIM];   // also reused as MoE hmid (compacted)
__device__ float g_k    [(size_t)NTOK*DIM];
__device__ float g_v    [(size_t)NTOK*DIM];
__device__ float g_attn [(size_t)NTOK*DIM];
__device__ float g_comb [(size_t)NTOK*NE];
__device__ int   g_cnt  [NE];
__device__ int   g_idx  [NE*NTOK];

__device__ __forceinline__ uint32_t f2tf32(float x) {
    uint32_t u;
    asm("cvt.rna.tf32.f32 %0, %1;" : "=r"(u) : "f"(x));
    return u;
}
__device__ __forceinline__ float tf32r(float x) { return __uint_as_float(f2tf32(x)); }

__device__ __forceinline__ void mma_tf32(float d[4], uint32_t a0, uint32_t a1,
                                         uint32_t a2, uint32_t a3,
                                         uint32_t b0, uint32_t b1) {
    asm volatile(
        "mma.sync.aligned.m16n8k8.row.col.f32.tf32.tf32.f32 "
        "{%0,%1,%2,%3}, {%4,%5,%6,%7}, {%8,%9}, {%0,%1,%2,%3};"
        : "+f"(d[0]), "+f"(d[1]), "+f"(d[2]), "+f"(d[3])
        : "r"(a0), "r"(a1), "r"(a2), "r"(a3), "r"(b0), "r"(b1));
}

__device__ __forceinline__ void mma_bf16(float d[4], uint32_t a0, uint32_t a1,
                                         uint32_t a2, uint32_t a3,
                                         uint32_t b0, uint32_t b1) {
    asm volatile(
        "mma.sync.aligned.m16n8k16.row.col.f32.bf16.bf16.f32 "
        "{%0,%1,%2,%3}, {%4,%5,%6,%7}, {%8,%9}, {%0,%1,%2,%3};"
        : "+f"(d[0]), "+f"(d[1]), "+f"(d[2]), "+f"(d[3])
        : "r"(a0), "r"(a1), "r"(a2), "r"(a3), "r"(b0), "r"(b1));
}

__device__ __forceinline__ uint32_t pack_bf2(float lo, float hi) {
    __nv_bfloat162 t = __floats2bfloat162_rn(lo, hi);   // .x = lo (low half)
    return *(uint32_t*)&t;
}
__device__ __forceinline__ uint16_t bf16bits(float x) {
    __nv_bfloat16 t = __float2bfloat16_rn(x);
    return *(uint16_t*)&t;
}

// ---------------- LayerNorm ----------------
__global__ void ln_kernel(const float* __restrict__ x, const float* __restrict__ w,
                          const float* __restrict__ b, float* __restrict__ y) {
    int row = blockIdx.x;
    const float* xr = x + (size_t)row * DIM;
    float* yr = y + (size_t)row * DIM;
    __shared__ float red[256];
    int tid = threadIdx.x;
    float s = 0.f;
    for (int i = tid; i < DIM; i += 256) s += xr[i];
    red[tid] = s; __syncthreads();
    for (int o = 128; o > 0; o >>= 1) { if (tid < o) red[tid] += red[tid + o]; __syncthreads(); }
    float mu = red[0] * (1.f / DIM);
    __syncthreads();
    float v = 0.f;
    for (int i = tid; i < DIM; i += 256) { float d = xr[i] - mu; v += d * d; }
    red[tid] = v; __syncthreads();
    for (int o = 128; o > 0; o >>= 1) { if (tid < o) red[tid] += red[tid + o]; __syncthreads(); }
    float inv = rsqrtf(red[0] * (1.f / DIM) + 1e-5f);
    for (int i = tid; i < DIM; i += 256) yr[i] = (xr[i] - mu) * inv * w[i] + b[i];
}

// ---------------- TF32 tensor-core GEMM with optional row gather/scatter ---------------
// C[cmap[m], :] (or C[m,:]) = act(A[amap[m],:] (or A[m,:]) @ B + bias) [+resid] [*rowscale[cr]]
// If mcount != null, effective M = *mcount; blocks beyond it exit.
__device__ __forceinline__ void epi(float v, int gm, int gn,
                                    const float* bias, int act,
                                    const float* resid, int ldr,
                                    const float* rowscale, int rss,
                                    float* C, int ldc, int accum) {
    if (bias) v += bias[gn];
    if (act) v = 0.5f * v * (1.f + erff(v * 0.70710678118654752f));
    if (resid) v += resid[(size_t)gm * ldr + gn];
    if (rowscale) v *= rowscale[(size_t)gm * rss];
    size_t o = (size_t)gm * ldc + gn;
    if (accum) C[o] += v; else C[o] = v;
}

__global__ void __launch_bounds__(256)
gemm_tf32(const float* __restrict__ A, int lda,
          const float* __restrict__ B, int ldb,
          const float* __restrict__ bias,
          float* __restrict__ C, int ldc,
          const float* __restrict__ resid, int ldr,
          const float* __restrict__ rowscale, int rss,
          int M, int N, int K, int act, int accum,
          const int* __restrict__ amap, const int* __restrict__ cmap,
          const int* __restrict__ mcount) {
    int M_eff = mcount ? *mcount : M;
    int row0 = blockIdx.y * 128, col0 = blockIdx.x * 128;
    if (row0 >= M_eff) return;

    __shared__ float As[128][20];
    __shared__ float Bs[16][136];
    int tid = threadIdx.x;
    int w = tid >> 5, lane = tid & 31;
    int wm = w >> 2, wn = w & 3;
    int m_w = wm * 64, n_w = wn * 32;
    int g = lane >> 2, q = lane & 3;

    float acc[4][4][4];
#pragma unroll
    for (int i = 0; i < 4; i++)
#pragma unroll
        for (int j = 0; j < 4; j++)
#pragma unroll
            for (int r = 0; r < 4; r++) acc[i][j][r] = 0.f;

    int a_row0 = tid >> 2,  a_c0 = (tid & 3) * 4;
    int a_row1 = (tid + 256) >> 2, a_c1 = ((tid + 256) & 3) * 4;
    int b_row0 = tid >> 5,  b_c0 = (tid & 31) * 4;
    int b_row1 = (tid + 256) >> 5, b_c1 = ((tid + 256) & 31) * 4;

    int gr0 = row0 + a_row0, gr1 = row0 + a_row1;
    int cl0 = gr0 < M_eff ? gr0 : M_eff - 1;
    int cl1 = gr1 < M_eff ? gr1 : M_eff - 1;
    int ar0 = amap ? amap[cl0] : cl0;
    int ar1 = amap ? amap[cl1] : cl1;

    const float* Ap0 = A + (size_t)ar0 * lda + a_c0;
    const float* Ap1 = A + (size_t)ar1 * lda + a_c1;
    const float* Bp0 = B + (size_t)b_row0 * ldb + col0 + b_c0;
    const float* Bp1 = B + (size_t)b_row1 * ldb + col0 + b_c1;

    float4 pa0 = *(const float4*)Ap0;
    float4 pa1 = *(const float4*)Ap1;
    float4 pb0 = *(const float4*)Bp0;
    float4 pb1 = *(const float4*)Bp1;

    for (int k0 = 0; k0 < K; k0 += 16) {
        As[a_row0][a_c0 + 0] = tf32r(pa0.x);
        As[a_row0][a_c0 + 1] = tf32r(pa0.y);
        As[a_row0][a_c0 + 2] = tf32r(pa0.z);
        As[a_row0][a_c0 + 3] = tf32r(pa0.w);
        As[a_row1][a_c1 + 0] = tf32r(pa1.x);
        As[a_row1][a_c1 + 1] = tf32r(pa1.y);
        As[a_row1][a_c1 + 2] = tf32r(pa1.z);
        As[a_row1][a_c1 + 3] = tf32r(pa1.w);
        Bs[b_row0][b_c0 + 0] = tf32r(pb0.x);
        Bs[b_row0][b_c0 + 1] = tf32r(pb0.y);
        Bs[b_row0][b_c0 + 2] = tf32r(pb0.z);
        Bs[b_row0][b_c0 + 3] = tf32r(pb0.w);
        Bs[b_row1][b_c1 + 0] = tf32r(pb1.x);
        Bs[b_row1][b_c1 + 1] = tf32r(pb1.y);
        Bs[b_row1][b_c1 + 2] = tf32r(pb1.z);
        Bs[b_row1][b_c1 + 3] = tf32r(pb1.w);
        __syncthreads();

        if (k0 + 16 < K) {
            pa0 = *(const float4*)(Ap0 + k0 + 16);
            pa1 = *(const float4*)(Ap1 + k0 + 16);
            pb0 = *(const float4*)(Bp0 + (size_t)(k0 + 16) * ldb);
            pb1 = *(const float4*)(Bp1 + (size_t)(k0 + 16) * ldb);
        }

#pragma unroll
        for (int ks = 0; ks < 2; ks++) {
            int kb = ks * 8;
            uint32_t af[4][4], bf[4][2];
#pragma unroll
            for (int i = 0; i < 4; i++) {
                int r = m_w + i * 16 + g;
                af[i][0] = __float_as_uint(As[r][kb + q]);
                af[i][1] = __float_as_uint(As[r + 8][kb + q]);
                af[i][2] = __float_as_uint(As[r][kb + q + 4]);
                af[i][3] = __float_as_uint(As[r + 8][kb + q + 4]);
            }
#pragma unroll
            for (int j = 0; j < 4; j++) {
                int c = n_w + j * 8 + g;
                bf[j][0] = __float_as_uint(Bs[kb + q][c]);
                bf[j][1] = __float_as_uint(Bs[kb + q + 4][c]);
            }
#pragma unroll
            for (int i = 0; i < 4; i++)
#pragma unroll
                for (int j = 0; j < 4; j++)
                    mma_tf32(acc[i][j], af[i][0], af[i][1], af[i][2], af[i][3],
                             bf[j][0], bf[j][1]);
        }
        __syncthreads();
    }

#pragma unroll
    for (int i = 0; i < 4; i++) {
        int gm = row0 + m_w + i * 16 + g;
        if (gm >= M_eff) continue;
        int cr = cmap ? cmap[gm] : gm;
#pragma unroll
        for (int j = 0; j < 4; j++) {
            int cb = col0 + n_w + j * 8 + q * 2;
            epi(acc[i][j][0], cr, cb,     bias, act, resid, ldr, rowscale, rss, C, ldc, accum);
            epi(acc[i][j][1], cr, cb + 1, bias, act, resid, ldr, rowscale, rss, C, ldc, accum);
        }
        int gm2 = gm + 8;
        if (gm2 >= M_eff) continue;
        int cr2 = cmap ? cmap[gm2] : gm2;
#pragma unroll
        for (int j = 0; j < 4; j++) {
            int cb = col0 + n_w + j * 8 + q * 2;
            epi(acc[i][j][2], cr2, cb,     bias, act, resid, ldr, rowscale, rss, C, ldc, accum);
            epi(acc[i][j][3], cr2, cb + 1, bias, act, resid, ldr, rowscale, rss, C, ldc, accum);
        }
    }
}

// ---------------- RoPE ----------------------------------------------------------------
__global__ void rope_kernel(float* __restrict__ q, float* __restrict__ k) {
    int idx = blockIdx.x * blockDim.x + threadIdx.x;
    if (idx >= NTOK * NH * 64) return;
    int i = idx & 63;
    int rem = idx >> 6;
    int h = rem % NH;
    int t = rem / NH;
    int s = t % SEQ;
    float invf = (float)(1.0 / pow(10000.0, (double)i / 64.0));
    float ang = (float)s * invf;
    double angd = (double)ang;
    float c  = (float)cos(angd);
    float sn = (float)sin(angd);
    size_t base = (size_t)t * DIM + (size_t)h * HDIM;
    float q1 = q[base + i], q2 = q[base + 64 + i];
    q[base + i]      = q1 * c - q2 * sn;
    q[base + 64 + i] = q2 * c + q1 * sn;
    float k1 = k[base + i], k2 = k[base + 64 + i];
    k[base + i]      = k1 * c - k2 * sn;
    k[base + 64 + i] = k2 * c + k1 * sn;
}

// ---------------- Flash attention, bf16 MMA, 4 warps (R5, proven) ----------------------
__global__ void __launch_bounds__(128)
fa_kernel(const float* __restrict__ q, const float* __restrict__ k,
          const float* __restrict__ v, float* __restrict__ attn) {
    __shared__ uint32_t Qs[64][68];
    __shared__ uint32_t Ks[32][68];
    __shared__ uint32_t Vt[128][20];
    __shared__ uint32_t Ps[4][16][20];

    int bh = blockIdx.y;
    int b = bh / NH, h = bh % NH;
    int q0 = blockIdx.x * 64;
    int tid = threadIdx.x, w = tid >> 5, lane = tid & 31;
    int g = lane >> 2, qd = lane & 3;
    const float alpha = 0.08838834764831845f;

    const float* qb = q + ((size_t)b * SEQ) * DIM + h * HDIM;
    const float* kb_ = k + ((size_t)b * SEQ) * DIM + h * HDIM;
    const float* vb = v + ((size_t)b * SEQ) * DIM + h * HDIM;

    for (int i = tid; i < 64 * 32; i += 128) {
        int r = i >> 5, c4 = i & 31;
        float4 t = *(const float4*)(qb + (size_t)(q0 + r) * DIM + c4 * 4);
        Qs[r][c4 * 2]     = pack_bf2(t.x * alpha, t.y * alpha);
        Qs[r][c4 * 2 + 1] = pack_bf2(t.z * alpha, t.w * alpha);
    }

    float m0 = -1e30f, m1 = -1e30f, l0 = 0.f, l1 = 0.f;
    float out[16][4];
#pragma unroll
    for (int i = 0; i < 16; i++)
#pragma unroll
        for (int r = 0; r < 4; r++) out[i][r] = 0.f;

    int ktiles = q0 / 32 + 2;

    for (int kt = 0; kt < ktiles; kt++) {
        int k0 = kt * 32;
        __syncthreads();
        for (int i = tid; i < 32 * 32; i += 128) {
            int r = i >> 5, c4 = i & 31;
            float4 tk = *(const float4*)(kb_ + (size_t)(k0 + r) * DIM + c4 * 4);
            Ks[r][c4 * 2]     = pack_bf2(tk.x, tk.y);
            Ks[r][c4 * 2 + 1] = pack_bf2(tk.z, tk.w);
            float4 tv = *(const float4*)(vb + (size_t)(k0 + r) * DIM + c4 * 4);
            uint16_t* vt = (uint16_t*)Vt;
            vt[(c4 * 4 + 0) * 40 + r] = bf16bits(tv.x);
            vt[(c4 * 4 + 1) * 40 + r] = bf16bits(tv.y);
            vt[(c4 * 4 + 2) * 40 + r] = bf16bits(tv.z);
            vt[(c4 * 4 + 3) * 40 + r] = bf16bits(tv.w);
        }
        __syncthreads();

        float sc[4][4];
#pragma unroll
        for (int nt = 0; nt < 4; nt++)
#pragma unroll
            for (int r = 0; r < 4; r++) sc[nt][r] = 0.f;
#pragma unroll
        for (int ks = 0; ks < 8; ks++) {
            int kp = ks * 8;
            uint32_t a0 = Qs[w * 16 + g][kp + qd];
            uint32_t a1 = Qs[w * 16 + g + 8][kp + qd];
            uint32_t a2 = Qs[w * 16 + g][kp + qd + 4];
            uint32_t a3 = Qs[w * 16 + g + 8][kp + qd + 4];
#pragma unroll
            for (int nt = 0; nt < 4; nt++) {
                uint32_t b0 = Ks[nt * 8 + g][kp + qd];
                uint32_t b1 = Ks[nt * 8 + g][kp + qd + 4];
                mma_bf16(sc[nt], a0, a1, a2, a3, b0, b1);
            }
        }

        if (k0 + 31 > q0) {
            int rq0 = q0 + w * 16 + g;
            int rq1 = rq0 + 8;
#pragma unroll
            for (int nt = 0; nt < 4; nt++) {
                int kc = k0 + nt * 8 + qd * 2;
                if (kc     > rq0) sc[nt][0] = -1e30f;
                if (kc + 1 > rq0) sc[nt][1] = -1e30f;
                if (kc     > rq1) sc[nt][2] = -1e30f;
                if (kc + 1 > rq1) sc[nt][3] = -1e30f;
            }
        }

        float tm0 = -1e30f, tm1 = -1e30f;
#pragma unroll
        for (int nt = 0; nt < 4; nt++) {
            tm0 = fmaxf(tm0, fmaxf(sc[nt][0], sc[nt][1]));
            tm1 = fmaxf(tm1, fmaxf(sc[nt][2], sc[nt][3]));
        }
        tm0 = fmaxf(tm0, __shfl_xor_sync(0xffffffffu, tm0, 1));
        tm0 = fmaxf(tm0, __shfl_xor_sync(0xffffffffu, tm0, 2));
        tm1 = fmaxf(tm1, __shfl_xor_sync(0xffffffffu, tm1, 1));
        tm1 = fmaxf(tm1, __shfl_xor_sync(0xffffffffu, tm1, 2));

        float mn0 = fmaxf(m0, tm0), mn1 = fmaxf(m1, tm1);
        float corr0 = expf(m0 - mn0), corr1 = expf(m1 - mn1);
        m0 = mn0; m1 = mn1;
        l0 *= corr0; l1 *= corr1;
#pragma unroll
        for (int nt = 0; nt < 16; nt++) {
            out[nt][0] *= corr0; out[nt][1] *= corr0;
            out[nt][2] *= corr1; out[nt][3] *= corr1;
        }

        float s0 = 0.f, s1 = 0.f;
#pragma unroll
        for (int nt = 0; nt < 4; nt++) {
            float p0 = expf(sc[nt][0] - m0);
            float p1 = expf(sc[nt][1] - m0);
            float p2 = expf(sc[nt][2] - m1);
            float p3 = expf(sc[nt][3] - m1);
            s0 += p0 + p1; s1 += p2 + p3;
            Ps[w][g][nt * 4 + qd]     = pack_bf2(p0, p1);
            Ps[w][g + 8][nt * 4 + qd] = pack_bf2(p2, p3);
        }
        s0 += __shfl_xor_sync(0xffffffffu, s0, 1);
        s0 += __shfl_xor_sync(0xffffffffu, s0, 2);
        s1 += __shfl_xor_sync(0xffffffffu, s1, 1);
        s1 += __shfl_xor_sync(0xffffffffu, s1, 2);
        l0 += s0; l1 += s1;
        __syncwarp();

#pragma unroll
        for (int ks = 0; ks < 2; ks++) {
            int kp = ks * 8;
            uint32_t a0 = Ps[w][g][kp + qd];
            uint32_t a1 = Ps[w][g + 8][kp + qd];
            uint32_t a2 = Ps[w][g][kp + qd + 4];
            uint32_t a3 = Ps[w][g + 8][kp + qd + 4];
#pragma unroll
            for (int nt = 0; nt < 16; nt++) {
                uint32_t b0 = Vt[nt * 8 + g][kp + qd];
                uint32_t b1 = Vt[nt * 8 + g][kp + qd + 4];
                mma_bf16(out[nt], a0, a1, a2, a3, b0, b1);
            }
        }
        __syncwarp();
    }

    float inv0 = 1.f / l0, inv1 = 1.f / l1;
    int r0g = q0 + w * 16 + g;
    float* ob = attn + ((size_t)b * SEQ) * DIM + h * HDIM;
#pragma unroll
    for (int nt = 0; nt < 16; nt++) {
        int c = nt * 8 + qd * 2;
        *(float2*)(ob + (size_t)r0g * DIM + c) =
            make_float2(out[nt][0] * inv0, out[nt][1] * inv0);
        *(float2*)(ob + (size_t)(r0g + 8) * DIM + c) =
            make_float2(out[nt][2] * inv1, out[nt][3] * inv1);
    }
}

// ---------------- MoE gate -------------------------------------------------------------
__global__ void gate_kernel(const float* __restrict__ x, const float* __restrict__ wg,
                            float* __restrict__ comb) {
    int t = blockIdx.x;
    int tid = threadIdx.x;
    __shared__ float red[NE * 128];
    const float* xr = x + (size_t)t * DIM;
    float acc[NE] = {0.f, 0.f, 0.f, 0.f};
    for (int d = tid; d < DIM; d += 128) {
        float xv = xr[d];
#pragma unroll
        for (int e = 0; e < NE; e++) acc[e] += xv * wg[(size_t)d * NE + e];
    }
#pragma unroll
    for (int e = 0; e < NE; e++) red[e * 128 + tid] = acc[e];
    __syncthreads();
    for (int o = 64; o > 0; o >>= 1) {
        if (tid < o) {
#pragma unroll
            for (int e = 0; e < NE; e++) red[e * 128 + tid] += red[e * 128 + tid + o];
        }
        __syncthreads();
    }
    if (tid == 0) {
        float l[NE];
#pragma unroll
        for (int e = 0; e < NE; e++) l[e] = red[e * 128];
        float mx = fmaxf(fmaxf(l[0], l[1]), fmaxf(l[2], l[3]));
        float ex[NE], s = 0.f;
#pragma unroll
        for (int e = 0; e < NE; e++) { ex[e] = expf(l[e] - mx); s += ex[e]; }
        float p[NE];
#pragma unroll
        for (int e = 0; e < NE; e++) p[e] = ex[e] / s;
        int i0 = 0;
#pragma unroll
        for (int e = 1; e < NE; e++) if (p[e] > p[i0]) i0 = e;
        int i1 = (i0 == 0) ? 1 : 0;
#pragma unroll
        for (int e = 0; e < NE; e++) if (e != i0 && p[e] > p[i1]) i1 = e;
        float e1 = expf(p[i1] - p[i0]);
        float invs = 1.f / (1.f + e1);
        float c[NE] = {0.f, 0.f, 0.f, 0.f};
        c[i0] = invs;
        c[i1] = e1 * invs;
#pragma unroll
        for (int e = 0; e < NE; e++) comb[(size_t)t * NE + e] = c[e];
    }
}

// ---------------- Routing: build per-expert token lists --------------------------------
__global__ void zero_cnt_kernel(int* cnt) {
    if (threadIdx.x < NE) cnt[threadIdx.x] = 0;
}
__global__ void route_kernel(const float* __restrict__ comb, int* __restrict__ cnt,
                             int* __restrict__ idx) {
    int t = blockIdx.x * blockDim.x + threadIdx.x;
    if (t >= NTOK) return;
#pragma unroll
    for (int e = 0; e < NE; e++) {
        if (comb[(size_t)t * NE + e] > 0.f) {
            int pos = atomicAdd(&cnt[e], 1);
            idx[e * NTOK + pos] = t;
        }
    }
}

// ---------------- host orchestration ---------------------------------------------------
extern "C" void kernel_launch(void* const* d_in, const int* in_sizes, int n_in,
                              void* d_out, int out_size) {
    (void)in_sizes; (void)n_in; (void)out_size;
    const float* hs   = (const float*)d_in[0];
    const float* wq   = (const float*)d_in[1];
    const float* bq   = (const float*)d_in[2];
    const float* wk   = (const float*)d_in[3];
    const float* bk   = (const float*)d_in[4];
    const float* wv   = (const float*)d_in[5];
    const float* bv   = (const float*)d_in[6];
    const float* wo   = (const float*)d_in[7];
    const float* bo   = (const float*)d_in[8];
    const float* ln1w = (const float*)d_in[9];
    const float* ln1b = (const float*)d_in[10];
    const float* ln2w = (const float*)d_in[11];
    const float* ln2b = (const float*)d_in[12];
    const float* wg   = (const float*)d_in[13];
    const float* we1  = (const float*)d_in[14];
    const float* be1  = (const float*)d_in[15];
    const float* we2  = (const float*)d_in[16];
    const float* be2  = (const float*)d_in[17];
    float* out = (float*)d_out;

    float *p_ln, *p_q, *p_k, *p_v, *p_attn, *p_comb;
    int *p_cnt, *p_idx;
    cudaGetSymbolAddress((void**)&p_ln, g_ln);
    cudaGetSymbolAddress((void**)&p_q, g_q);
    cudaGetSymbolAddress((void**)&p_k, g_k);
    cudaGetSymbolAddress((void**)&p_v, g_v);
    cudaGetSymbolAddress((void**)&p_attn, g_attn);
    cudaGetSymbolAddress((void**)&p_comb, g_comb);
    cudaGetSymbolAddress((void**)&p_cnt, g_cnt);
    cudaGetSymbolAddress((void**)&p_idx, g_idx);

    // 1. LN1
    ln_kernel<<<NTOK, 256>>>(hs, ln1w, ln1b, p_ln);

    // 2. QKV projections (dense)
    dim3 gBig(DIM / 128, NTOK / 128);
    gemm_tf32<<<gBig, 256>>>(p_ln, DIM, wq, DIM, bq, p_q, DIM,
                             nullptr, 0, nullptr, 0, NTOK, DIM, DIM, 0, 0,
                             nullptr, nullptr, nullptr);
    gemm_tf32<<<gBig, 256>>>(p_ln, DIM, wk, DIM, bk, p_k, DIM,
                             nullptr, 0, nullptr, 0, NTOK, DIM, DIM, 0, 0,
                             nullptr, nullptr, nullptr);
    gemm_tf32<<<gBig, 256>>>(p_ln, DIM, wv, DIM, bv, p_v, DIM,
                             nullptr, 0, nullptr, 0, NTOK, DIM, DIM, 0, 0,
                             nullptr, nullptr, nullptr);

    // 3. RoPE
    int nrope = NTOK * NH * 64;
    rope_kernel<<<(nrope + 255) / 256, 256>>>(p_q, p_k);

    // 4. Flash attention
    dim3 gFA(SEQ / 64, BATCH * NH);
    fa_kernel<<<gFA, 128>>>(p_q, p_k, p_v, p_attn);

    // 5. O-proj + bias + residual -> out (= h)
    gemm_tf32<<<gBig, 256>>>(p_attn, DIM, wo, DIM, bo, out, DIM,
                             hs, DIM, nullptr, 0, NTOK, DIM, DIM, 0, 0,
                             nullptr, nullptr, nullptr);

    // 6. LN2
    ln_kernel<<<NTOK, 256>>>(out, ln2w, ln2b, p_ln);

    // 7. Gate + routing
    gate_kernel<<<NTOK, 128>>>(p_ln, wg, p_comb);
    zero_cnt_kernel<<<1, 32>>>(p_cnt);
    route_kernel<<<NTOK / 256, 256>>>(p_comb, p_cnt, p_idx);

    // 8. Sparse experts: only routed tokens.
    //    GEMM1: hmid[0..cnt) = gelu(x[idx] @ we1 + be1)  (gather A, dense C)
    //    GEMM2: out[idx] += comb[idx,e] * (hmid @ we2 + be2)  (dense A, scatter C)
    for (int e = 0; e < NE; e++) {
        const float* w1 = we1 + (size_t)e * DIM * IDIM;
        const float* b1 = be1 + (size_t)e * IDIM;
        const float* w2 = we2 + (size_t)e * IDIM * DIM;
        const float* b2 = be2 + (size_t)e * DIM;
        const int* idx_e = p_idx + e * NTOK;
        const int* cnt_e = p_cnt + e;
        gemm_tf32<<<gBig, 256>>>(p_ln, DIM, w1, IDIM, b1, p_q, IDIM,
                                 nullptr, 0, nullptr, 0, NTOK, IDIM, DIM, 1, 0,
                                 idx_e, nullptr, cnt_e);
        gemm_tf32<<<gBig, 256>>>(p_q, IDIM, w2, DIM, b2, out, DIM,
                                 nullptr, 0, p_comb + e, NE, NTOK, DIM, IDIM, 0, 1,
                                 nullptr, idx_e, cnt_e);
    }
}